// round 16
// baseline (speedup 1.0000x reference)
#include <cuda_runtime.h>
#include <cuda_fp16.h>
#include <math.h>

#define NN 4
#define CC 64
#define HH 256
#define WW 256
#define OC 18          // G*K*K
#define HW (HH*WW)
#define EPSF 1e-5f

// Scratch (device globals; zero-initialized at load; self-resetting).
__device__ float g_sigma[(size_t)NN * OC * HW];   // ~18.9 MB
__device__ float g_sum[OC], g_sumsq[OC], g_mean[OC], g_rstd[OC];
__device__ unsigned g_done;

// jnp.pad mode='reflect' (mirror, edge not repeated)
__device__ __forceinline__ int refl(int i, int n) {
    return i < 0 ? -i : (i >= n ? 2 * n - 2 - i : i);
}

// split two floats into packed f16 pairs: hi = RN(f16), lo = RN(residual).
__device__ __forceinline__ uint2 split2h(float v0, float v1) {
    __half2 h = __floats2half2_rn(v0, v1);
    float r0 = v0 - __half2float(__low2half(h));
    float r1 = v1 - __half2float(__high2half(h));
    __half2 l = __floats2half2_rn(r0, r1);
    uint2 r;
    r.x = *reinterpret_cast<unsigned*>(&h);
    r.y = *reinterpret_cast<unsigned*>(&l);
    return r;
}

#define MMAF16(d, a, b0, b1)                                                   \
    asm volatile(                                                              \
        "mma.sync.aligned.m16n8k16.row.col.f32.f16.f16.f32 "                   \
        "{%0,%1,%2,%3},{%4,%5,%6,%7},{%8,%9},{%0,%1,%2,%3};"                   \
        : "+f"(d[0]), "+f"(d[1]), "+f"(d[2]), "+f"(d[3])                       \
        : "r"(a[0]), "r"(a[1]), "r"(a[2]), "r"(a[3]), "r"(b0), "r"(b1))

// ---------------------------------------------------------------------------
// Conv via mma.sync f16, 2-term split (A hi/lo x B fp16). CTA = 256 thr,
// tile 128w x 4h; k = kb*80 + tap*8 + c. Staging vectorized: interior cols
// 1..128 are reflection-free & 16B-aligned -> float4 loads; cols 0/129 scalar.
// Weights converted inline; BN finalized by last CTA (self-resetting).
// ---------------------------------------------------------------------------
__global__ void __launch_bounds__(256, 2) k_conv(const float* __restrict__ y,
                                                 const float* __restrict__ wconv) {
    __shared__ uint2 ysp[6 * 132 * 4];       // 25344 B
    __shared__ unsigned bsp[40 * 24];        // 3840 B
    __shared__ float ssum[OC], ssq[OC];
    __shared__ unsigned slast;

    int tid = threadIdx.x;
    int warp = tid >> 5, lane = tid & 31;
    int g = lane >> 2, t = lane & 3;

    int w0 = blockIdx.x * 128;
    int h0 = blockIdx.y * 4;
    int n  = blockIdx.z;

    if (tid < OC) { ssum[tid] = 0.f; ssq[tid] = 0.f; }

    int grow[6];
#pragma unroll
    for (int r = 0; r < 6; r++) grow[r] = refl(h0 - 1 + r, HH) * WW;

    float acc[4][3][4];
#pragma unroll
    for (int a = 0; a < 4; a++)
#pragma unroll
        for (int b = 0; b < 3; b++)
#pragma unroll
            for (int d = 0; d < 4; d++) acc[a][b][d] = 0.f;

    int hh  = warp >> 1;
    int pxb = (warp & 1) * 64;

    for (int kb = 0; kb < 8; kb++) {
        __syncthreads();
        // stage B inline (fp16 single-rounded)
        for (int i = tid; i < 960; i += 256) {
            int o = i % 24, kp2 = i / 24;
            int tap = kp2 >> 2, cp = kp2 & 3;
            float v0 = 0.f, v1 = 0.f;
            if (tap < 9 && o < OC) {
                v0 = wconv[((size_t)o * CC + kb * 8 + 2 * cp) * 9 + tap];
                v1 = wconv[((size_t)o * CC + kb * 8 + 2 * cp + 1) * 9 + tap];
            }
            __half2 h = __floats2half2_rn(v0, v1);
            bsp[i] = *reinterpret_cast<unsigned*>(&h);
        }
        const float* ybase = y + ((size_t)(n * CC + kb * 8)) * HW;
        // interior: 6 rows x 32 float4-chunks x 4 channel-pairs = 768 tasks
        for (int i = tid; i < 768; i += 256) {
            int cp = i & 3, q = i >> 2;           // q: 0..191
            int row = q >> 5, j = q & 31;         // 32 chunks of 4 cols
            const float* p0 = ybase + (size_t)(2 * cp) * HW + grow[row] + w0 + 4 * j;
            float4 a = __ldg((const float4*)p0);
            float4 b = __ldg((const float4*)(p0 + HW));
            int base = (row * 132 + 1 + 4 * j) * 4 + cp;
            ysp[base]      = split2h(a.x, b.x);
            ysp[base + 4]  = split2h(a.y, b.y);
            ysp[base + 8]  = split2h(a.z, b.z);
            ysp[base + 12] = split2h(a.w, b.w);
        }
        // edges: cols 0 and 129 (reflected), 6 rows x 2 x 4 cp = 48 tasks
        if (tid < 48) {
            int cp = tid & 3, q = tid >> 2;       // q: 0..11
            int row = q >> 1, col = (q & 1) ? 129 : 0;
            int gw = refl(w0 - 1 + col, WW);
            const float* p0 = ybase + (size_t)(2 * cp) * HW + grow[row] + gw;
            ysp[(row * 132 + col) * 4 + cp] = split2h(__ldg(p0), __ldg(p0 + HW));
        }
        __syncthreads();

#pragma unroll
        for (int ch = 0; ch < 5; ch++) {
            const int tapA = 2 * ch;
            const int tapB = (2 * ch + 1 < 9) ? 2 * ch + 1 : 0;  // ch4 pad: B=0
            const int trA = tapA / 3, tcA = tapA % 3;
            const int trB = tapB / 3, tcB = tapB % 3;

            int aA = ((hh + trA) * 132 + pxb + g + tcA) * 4 + t;
            int aB = ((hh + trB) * 132 + pxb + g + tcB) * 4 + t;
            int bbase = (ch * 8 + t) * 24 + g;

            unsigned b0[3], b1[3];
#pragma unroll
            for (int nt = 0; nt < 3; nt++) {
                b0[nt] = bsp[bbase + nt * 8];
                b1[nt] = bsp[bbase + 96 + nt * 8];
            }

#pragma unroll
            for (int mt = 0; mt < 4; mt++) {
                int off = mt * 64;
                uint2 x0 = ysp[aA + off];
                uint2 x1 = ysp[aA + off + 32];
                uint2 x2 = ysp[aB + off];
                uint2 x3 = ysp[aB + off + 32];
                unsigned ah[4] = {x0.x, x1.x, x2.x, x3.x};
                unsigned al[4] = {x0.y, x1.y, x2.y, x3.y};
#pragma unroll
                for (int nt = 0; nt < 3; nt++) {
                    MMAF16(acc[mt][nt], ah, b0[nt], b1[nt]);
                    MMAF16(acc[mt][nt], al, b0[nt], b1[nt]);
                }
            }
        }
    }

    size_t sb = (size_t)n * OC * HW;
#pragma unroll
    for (int mt = 0; mt < 4; mt++)
#pragma unroll
        for (int nt = 0; nt < 3; nt++)
#pragma unroll
            for (int dd = 0; dd < 4; dd++) {
                int o = nt * 8 + 2 * t + (dd & 1);
                if (o < OC) {
                    int p = warp * 64 + mt * 16 + g + ((dd & 2) ? 8 : 0);
                    g_sigma[sb + (size_t)o * HW +
                            (size_t)(h0 + (p >> 7)) * WW + w0 + (p & 127)] =
                        acc[mt][nt][dd];
                }
            }

#pragma unroll
    for (int nt = 0; nt < 3; nt++)
#pragma unroll
        for (int d1 = 0; d1 < 2; d1++) {
            int o = nt * 8 + 2 * t + d1;
            float s = 0.f, q = 0.f;
#pragma unroll
            for (int mt = 0; mt < 4; mt++)
#pragma unroll
                for (int d2 = 0; d2 < 2; d2++) {
                    float v = acc[mt][nt][d2 * 2 + d1];
                    s += v; q += v * v;
                }
#pragma unroll
            for (int m = 4; m <= 16; m <<= 1) {
                s += __shfl_xor_sync(0xffffffffu, s, m);
                q += __shfl_xor_sync(0xffffffffu, q, m);
            }
            if (g == 0 && o < OC) { atomicAdd(&ssum[o], s); atomicAdd(&ssq[o], q); }
        }
    __syncthreads();
    if (tid < OC) { atomicAdd(&g_sum[tid], ssum[tid]); atomicAdd(&g_sumsq[tid], ssq[tid]); }

    __threadfence();
    if (tid == 0) {
        unsigned total = gridDim.x * gridDim.y * gridDim.z;
        slast = (atomicAdd(&g_done, 1u) == total - 1u);
    }
    __syncthreads();
    if (slast) {
        if (tid < OC) {
            float cnt = (float)((size_t)NN * HW);
            float s = atomicAdd(&g_sum[tid], 0.f);
            float q = atomicAdd(&g_sumsq[tid], 0.f);
            float m = s / cnt;
            float v = q / cnt - m * m;
            g_mean[tid] = m;
            g_rstd[tid] = rsqrtf(v + EPSF);
            atomicExch(&g_sum[tid], 0.f);
            atomicExch(&g_sumsq[tid], 0.f);
        }
        if (tid == 0) g_done = 0;
    }
}

// ---------------------------------------------------------------------------
// Stage 3: fused BN + softmax(18) + v_map + adaptive 3x3 filter.
// Edge values fetched from neighbor lanes via shuffle (warp covers 128
// contiguous px); only lanes 0/31 load the block-boundary scalars.
// ---------------------------------------------------------------------------
__global__ void __launch_bounds__(128, 5) k_apply(const float* __restrict__ y,
                                                  const float* __restrict__ gamma,
                                                  const float* __restrict__ beta,
                                                  float* __restrict__ out) {
    int tx = threadIdx.x, ty = threadIdx.y;
    int w0 = (blockIdx.x * 32 + tx) * 4;
    int h0 = blockIdx.y * 4 + ty;
    int n  = blockIdx.z;
    size_t pix = (size_t)h0 * WW + w0;

    float4 s4[OC];
    float4 mx = make_float4(-1e30f, -1e30f, -1e30f, -1e30f);
#pragma unroll
    for (int o = 0; o < OC; o++) {
        float4 x = *(const float4*)&g_sigma[((size_t)n * OC + o) * HW + pix];
        float sc = g_rstd[o] * __ldg(&gamma[o]);
        float m  = g_mean[o], b = __ldg(&beta[o]);
        x.x = (x.x - m) * sc + b; x.y = (x.y - m) * sc + b;
        x.z = (x.z - m) * sc + b; x.w = (x.w - m) * sc + b;
        s4[o] = x;
        mx.x = fmaxf(mx.x, x.x); mx.y = fmaxf(mx.y, x.y);
        mx.z = fmaxf(mx.z, x.z); mx.w = fmaxf(mx.w, x.w);
    }
    float4 sum = make_float4(0.f, 0.f, 0.f, 0.f);
#pragma unroll
    for (int o = 0; o < OC; o++) {
        s4[o].x = __expf(s4[o].x - mx.x); sum.x += s4[o].x;
        s4[o].y = __expf(s4[o].y - mx.y); sum.y += s4[o].y;
        s4[o].z = __expf(s4[o].z - mx.z); sum.z += s4[o].z;
        s4[o].w = __expf(s4[o].w - mx.w); sum.w += s4[o].w;
    }
    float4 inv = make_float4(1.f / sum.x, 1.f / sum.y, 1.f / sum.z, 1.f / sum.w);
#pragma unroll
    for (int o = 0; o < OC; o++) {
        s4[o].x *= inv.x; s4[o].y *= inv.y; s4[o].z *= inv.z; s4[o].w *= inv.w;
    }

    float* vmap = out + (size_t)NN * CC * HW;
#pragma unroll
    for (int o = 0; o < OC; o++)
        *(float4*)&vmap[((size_t)n * OC + o) * HW + pix] = s4[o];

    int rh[3];
#pragma unroll
    for (int i = 0; i < 3; i++) rh[i] = refl(h0 + i - 1, HH);
    int wl = refl(w0 - 1, WW);   // used by lane 0 only
    int wr = refl(w0 + 4, WW);   // used by lane 31 only

#pragma unroll
    for (int g = 0; g < 2; g++) {
#pragma unroll 2
        for (int cg = 0; cg < 32; cg++) {
            int c = g * 32 + cg;
            const float* yc = y + ((size_t)(n * CC + c)) * HW;
            float4 acc = make_float4(0.f, 0.f, 0.f, 0.f);
#pragma unroll
            for (int i = 0; i < 3; i++) {
                const float* row = yc + rh[i] * WW;
                float4 m = __ldg((const float4*)(row + w0));
                // edges from neighbor lanes (warp spans 128 contiguous px)
                float el = __shfl_up_sync(0xffffffffu, m.w, 1);
                float er = __shfl_down_sync(0xffffffffu, m.x, 1);
                if (tx == 0)  el = __ldg(&row[wl]);
                if (tx == 31) er = __ldg(&row[wr]);
                float v[6];
                v[0] = el; v[1] = m.x; v[2] = m.y;
                v[3] = m.z; v[4] = m.w; v[5] = er;
#pragma unroll
                for (int j = 0; j < 3; j++) {
                    float4 sw = s4[g * 9 + i * 3 + j];
                    acc.x += v[0 + j] * sw.x;
                    acc.y += v[1 + j] * sw.y;
                    acc.z += v[2 + j] * sw.z;
                    acc.w += v[3 + j] * sw.w;
                }
            }
            *(float4*)&out[((size_t)(n * CC + c)) * HW + pix] = acc;
        }
    }
}

extern "C" void kernel_launch(void* const* d_in, const int* in_sizes, int n_in,
                              void* d_out, int out_size) {
    const float* y     = (const float*)d_in[0];
    const float* w     = (const float*)d_in[1];
    const float* gamma = (const float*)d_in[2];
    const float* beta  = (const float*)d_in[3];
    float* out = (float*)d_out;

    dim3 cgrd(WW / 128, HH / 4, NN);    // 512 CTAs
    k_conv<<<cgrd, 256>>>(y, w);

    dim3 ablk(32, 4), agrd(WW / 128, HH / 4, NN);
    k_apply<<<agrd, ablk>>>(y, gamma, beta, out);
}

// round 17
// speedup vs baseline: 1.7928x; 1.7928x over previous
#include <cuda_runtime.h>
#include <cuda_fp16.h>
#include <math.h>

#define NN 4
#define CC 64
#define HH 256
#define WW 256
#define OC 18          // G*K*K
#define HW (HH*WW)
#define EPSF 1e-5f

// Scratch (device globals; zero-initialized at load; self-resetting).
__device__ float g_sigma[(size_t)NN * OC * HW];   // ~18.9 MB
__device__ float g_sum[OC], g_sumsq[OC], g_mean[OC], g_rstd[OC];
__device__ unsigned g_done;

// jnp.pad mode='reflect' (mirror, edge not repeated)
__device__ __forceinline__ int refl(int i, int n) {
    return i < 0 ? -i : (i >= n ? 2 * n - 2 - i : i);
}

__device__ __forceinline__ unsigned pack2h(float v0, float v1) {
    __half2 h = __floats2half2_rn(v0, v1);
    return *reinterpret_cast<unsigned*>(&h);
}

#define MMAF16(d, a, b0, b1)                                                   \
    asm volatile(                                                              \
        "mma.sync.aligned.m16n8k16.row.col.f32.f16.f16.f32 "                   \
        "{%0,%1,%2,%3},{%4,%5,%6,%7},{%8,%9},{%0,%1,%2,%3};"                   \
        : "+f"(d[0]), "+f"(d[1]), "+f"(d[2]), "+f"(d[3])                       \
        : "r"(a[0]), "r"(a[1]), "r"(a[2]), "r"(a[3]), "r"(b0), "r"(b1))

// ---------------------------------------------------------------------------
// Conv via mma.sync f16, single-term (A fp16 x B fp16; error ~sqrt2 x 2-term's
// B-only rounding, ~2.4e-4 << 1e-3). CTA = 256 thr, tile 128w x 4h;
// k = kb*80 + tap*8 + c. Vectorized staging (interior float4, edge scalars).
// Weights converted inline; BN finalized by last CTA (self-resetting).
// ---------------------------------------------------------------------------
__global__ void __launch_bounds__(256, 2) k_conv(const float* __restrict__ y,
                                                 const float* __restrict__ wconv) {
    __shared__ unsigned ysp[6 * 132 * 4];    // 12672 B (fp16x2, ch pairs)
    __shared__ unsigned bsp[40 * 24];        // 3840 B
    __shared__ float ssum[OC], ssq[OC];
    __shared__ unsigned slast;

    int tid = threadIdx.x;
    int warp = tid >> 5, lane = tid & 31;
    int g = lane >> 2, t = lane & 3;

    int w0 = blockIdx.x * 128;
    int h0 = blockIdx.y * 4;
    int n  = blockIdx.z;

    if (tid < OC) { ssum[tid] = 0.f; ssq[tid] = 0.f; }

    int grow[6];
#pragma unroll
    for (int r = 0; r < 6; r++) grow[r] = refl(h0 - 1 + r, HH) * WW;

    float acc[4][3][4];
#pragma unroll
    for (int a = 0; a < 4; a++)
#pragma unroll
        for (int b = 0; b < 3; b++)
#pragma unroll
            for (int d = 0; d < 4; d++) acc[a][b][d] = 0.f;

    int hh  = warp >> 1;
    int pxb = (warp & 1) * 64;

    for (int kb = 0; kb < 8; kb++) {
        __syncthreads();
        // stage B inline (fp16 single-rounded)
        for (int i = tid; i < 960; i += 256) {
            int o = i % 24, kp2 = i / 24;
            int tap = kp2 >> 2, cp = kp2 & 3;
            float v0 = 0.f, v1 = 0.f;
            if (tap < 9 && o < OC) {
                v0 = wconv[((size_t)o * CC + kb * 8 + 2 * cp) * 9 + tap];
                v1 = wconv[((size_t)o * CC + kb * 8 + 2 * cp + 1) * 9 + tap];
            }
            bsp[i] = pack2h(v0, v1);
        }
        const float* ybase = y + ((size_t)(n * CC + kb * 8)) * HW;
        // interior: 6 rows x 32 float4-chunks x 4 channel-pairs
        for (int i = tid; i < 768; i += 256) {
            int cp = i & 3, q = i >> 2;
            int row = q >> 5, j = q & 31;
            const float* p0 = ybase + (size_t)(2 * cp) * HW + grow[row] + w0 + 4 * j;
            float4 a = __ldg((const float4*)p0);
            float4 b = __ldg((const float4*)(p0 + HW));
            int base = (row * 132 + 1 + 4 * j) * 4 + cp;
            ysp[base]      = pack2h(a.x, b.x);
            ysp[base + 4]  = pack2h(a.y, b.y);
            ysp[base + 8]  = pack2h(a.z, b.z);
            ysp[base + 12] = pack2h(a.w, b.w);
        }
        // edges: cols 0 and 129 (reflected)
        if (tid < 48) {
            int cp = tid & 3, q = tid >> 2;
            int row = q >> 1, col = (q & 1) ? 129 : 0;
            int gw = refl(w0 - 1 + col, WW);
            const float* p0 = ybase + (size_t)(2 * cp) * HW + grow[row] + gw;
            ysp[(row * 132 + col) * 4 + cp] = pack2h(__ldg(p0), __ldg(p0 + HW));
        }
        __syncthreads();

#pragma unroll
        for (int ch = 0; ch < 5; ch++) {
            const int tapA = 2 * ch;
            const int tapB = (2 * ch + 1 < 9) ? 2 * ch + 1 : 0;  // ch4 pad: B=0
            const int trA = tapA / 3, tcA = tapA % 3;
            const int trB = tapB / 3, tcB = tapB % 3;

            int aA = ((hh + trA) * 132 + pxb + g + tcA) * 4 + t;
            int aB = ((hh + trB) * 132 + pxb + g + tcB) * 4 + t;
            int bbase = (ch * 8 + t) * 24 + g;

            unsigned b0[3], b1[3];
#pragma unroll
            for (int nt = 0; nt < 3; nt++) {
                b0[nt] = bsp[bbase + nt * 8];
                b1[nt] = bsp[bbase + 96 + nt * 8];
            }

#pragma unroll
            for (int mt = 0; mt < 4; mt++) {
                int off = mt * 64;
                unsigned ah[4];
                ah[0] = ysp[aA + off];
                ah[1] = ysp[aA + off + 32];
                ah[2] = ysp[aB + off];
                ah[3] = ysp[aB + off + 32];
#pragma unroll
                for (int nt = 0; nt < 3; nt++)
                    MMAF16(acc[mt][nt], ah, b0[nt], b1[nt]);
            }
        }
    }

    size_t sb = (size_t)n * OC * HW;
#pragma unroll
    for (int mt = 0; mt < 4; mt++)
#pragma unroll
        for (int nt = 0; nt < 3; nt++)
#pragma unroll
            for (int dd = 0; dd < 4; dd++) {
                int o = nt * 8 + 2 * t + (dd & 1);
                if (o < OC) {
                    int p = warp * 64 + mt * 16 + g + ((dd & 2) ? 8 : 0);
                    g_sigma[sb + (size_t)o * HW +
                            (size_t)(h0 + (p >> 7)) * WW + w0 + (p & 127)] =
                        acc[mt][nt][dd];
                }
            }

#pragma unroll
    for (int nt = 0; nt < 3; nt++)
#pragma unroll
        for (int d1 = 0; d1 < 2; d1++) {
            int o = nt * 8 + 2 * t + d1;
            float s = 0.f, q = 0.f;
#pragma unroll
            for (int mt = 0; mt < 4; mt++)
#pragma unroll
                for (int d2 = 0; d2 < 2; d2++) {
                    float v = acc[mt][nt][d2 * 2 + d1];
                    s += v; q += v * v;
                }
#pragma unroll
            for (int m = 4; m <= 16; m <<= 1) {
                s += __shfl_xor_sync(0xffffffffu, s, m);
                q += __shfl_xor_sync(0xffffffffu, q, m);
            }
            if (g == 0 && o < OC) { atomicAdd(&ssum[o], s); atomicAdd(&ssq[o], q); }
        }
    __syncthreads();
    if (tid < OC) { atomicAdd(&g_sum[tid], ssum[tid]); atomicAdd(&g_sumsq[tid], ssq[tid]); }

    __threadfence();
    if (tid == 0) {
        unsigned total = gridDim.x * gridDim.y * gridDim.z;
        slast = (atomicAdd(&g_done, 1u) == total - 1u);
    }
    __syncthreads();
    if (slast) {
        if (tid < OC) {
            float cnt = (float)((size_t)NN * HW);
            float s = atomicAdd(&g_sum[tid], 0.f);
            float q = atomicAdd(&g_sumsq[tid], 0.f);
            float m = s / cnt;
            float v = q / cnt - m * m;
            g_mean[tid] = m;
            g_rstd[tid] = rsqrtf(v + EPSF);
            atomicExch(&g_sum[tid], 0.f);
            atomicExch(&g_sumsq[tid], 0.f);
        }
        if (tid == 0) g_done = 0;
    }
}

// ---------------------------------------------------------------------------
// Stage 3: fused BN + softmax(18) + v_map + adaptive 3x3 filter — EXACT R15
// version (measured best, 40 us; shuffle/multipass variants all regressed).
// ---------------------------------------------------------------------------
__global__ void __launch_bounds__(128) k_apply(const float* __restrict__ y,
                                               const float* __restrict__ gamma,
                                               const float* __restrict__ beta,
                                               float* __restrict__ out) {
    int tx = threadIdx.x, ty = threadIdx.y;
    int w0 = (blockIdx.x * 32 + tx) * 4;
    int h0 = blockIdx.y * 4 + ty;
    int n  = blockIdx.z;
    size_t pix = (size_t)h0 * WW + w0;

    float4 s4[OC];
    float4 mx = make_float4(-1e30f, -1e30f, -1e30f, -1e30f);
#pragma unroll
    for (int o = 0; o < OC; o++) {
        float4 x = *(const float4*)&g_sigma[((size_t)n * OC + o) * HW + pix];
        float sc = g_rstd[o] * __ldg(&gamma[o]);
        float m  = g_mean[o], b = __ldg(&beta[o]);
        x.x = (x.x - m) * sc + b; x.y = (x.y - m) * sc + b;
        x.z = (x.z - m) * sc + b; x.w = (x.w - m) * sc + b;
        s4[o] = x;
        mx.x = fmaxf(mx.x, x.x); mx.y = fmaxf(mx.y, x.y);
        mx.z = fmaxf(mx.z, x.z); mx.w = fmaxf(mx.w, x.w);
    }
    float4 sum = make_float4(0.f, 0.f, 0.f, 0.f);
#pragma unroll
    for (int o = 0; o < OC; o++) {
        s4[o].x = __expf(s4[o].x - mx.x); sum.x += s4[o].x;
        s4[o].y = __expf(s4[o].y - mx.y); sum.y += s4[o].y;
        s4[o].z = __expf(s4[o].z - mx.z); sum.z += s4[o].z;
        s4[o].w = __expf(s4[o].w - mx.w); sum.w += s4[o].w;
    }
    float4 inv = make_float4(1.f / sum.x, 1.f / sum.y, 1.f / sum.z, 1.f / sum.w);
#pragma unroll
    for (int o = 0; o < OC; o++) {
        s4[o].x *= inv.x; s4[o].y *= inv.y; s4[o].z *= inv.z; s4[o].w *= inv.w;
    }

    float* vmap = out + (size_t)NN * CC * HW;
#pragma unroll
    for (int o = 0; o < OC; o++)
        *(float4*)&vmap[((size_t)n * OC + o) * HW + pix] = s4[o];

    int rh[3];
#pragma unroll
    for (int i = 0; i < 3; i++) rh[i] = refl(h0 + i - 1, HH);
    int wl = refl(w0 - 1, WW);
    int wr = refl(w0 + 4, WW);

#pragma unroll
    for (int g = 0; g < 2; g++) {
#pragma unroll 2
        for (int cg = 0; cg < 32; cg++) {
            int c = g * 32 + cg;
            const float* yc = y + ((size_t)(n * CC + c)) * HW;
            float4 acc = make_float4(0.f, 0.f, 0.f, 0.f);
#pragma unroll
            for (int i = 0; i < 3; i++) {
                const float* row = yc + rh[i] * WW;
                float4 m = __ldg((const float4*)(row + w0));
                float v[6];
                v[0] = __ldg(&row[wl]); v[1] = m.x; v[2] = m.y;
                v[3] = m.z; v[4] = m.w; v[5] = __ldg(&row[wr]);
#pragma unroll
                for (int j = 0; j < 3; j++) {
                    float4 sw = s4[g * 9 + i * 3 + j];
                    acc.x += v[0 + j] * sw.x;
                    acc.y += v[1 + j] * sw.y;
                    acc.z += v[2 + j] * sw.z;
                    acc.w += v[3 + j] * sw.w;
                }
            }
            *(float4*)&out[((size_t)(n * CC + c)) * HW + pix] = acc;
        }
    }
}

extern "C" void kernel_launch(void* const* d_in, const int* in_sizes, int n_in,
                              void* d_out, int out_size) {
    const float* y     = (const float*)d_in[0];
    const float* w     = (const float*)d_in[1];
    const float* gamma = (const float*)d_in[2];
    const float* beta  = (const float*)d_in[3];
    float* out = (float*)d_out;

    dim3 cgrd(WW / 128, HH / 4, NN);    // 512 CTAs
    k_conv<<<cgrd, 256>>>(y, w);

    dim3 ablk(32, 4), agrd(WW / 128, HH / 4, NN);
    k_apply<<<agrd, ablk>>>(y, gamma, beta, out);
}